// round 12
// baseline (speedup 1.0000x reference)
#include <cuda_runtime.h>
#include <cuda_fp16.h>
#include <mma.h>
#include <math.h>

using namespace nvcuda;

#define NMAX 50000
#define EMAX 800000
#define HID  128
#define CO   40

// ---------------- scratch (device globals) ----------------
__device__ __align__(16) __half g_hA[NMAX * HID];   // gemm output (gather src)
__device__ __align__(16) __half g_hB[NMAX * HID];   // agg output (gemm A src)
__device__ __align__(16) __half g_h3[NMAX * CO];
__device__ __align__(16) float  g_dinv[NMAX];
__device__ int   g_cnt[NMAX];
__device__ int   g_off[NMAX + 1];
__device__ int   g_cur[NMAX];
__device__ int   g_csr_src[EMAX + NMAX];
__device__ float g_csr_coef[EMAX + NMAX];
__device__ __align__(16) float g_stats[2 * 256];    // slots: [sum128, sumsq128] x2
__device__ volatile int g_scan_flag[64];
__device__ volatile int g_scan_psum[64];

// ---------------- init: cnt=1 (self loop), zero stats + scan flags ---------
__global__ void deg_init(int n) {
    int i = blockIdx.x * blockDim.x + threadIdx.x;
    if (i < n) g_cnt[i] = 1;
    if (i < 512) g_stats[i] = 0.0f;
    if (i < 64) { g_scan_flag[i] = 0; g_scan_psum[i] = 0; }
}
__global__ void deg_count(const int* __restrict__ ei, int e) {
    int i = blockIdx.x * blockDim.x + threadIdx.x;
    if (i < e) atomicAdd(&g_cnt[ei[e + i]], 1);
}

// ---- fused scan: block scan + decoupled-lookback prefix + dinv + self-scatter
__global__ void scan_fused(int n) {
    __shared__ int wsum[32];
    __shared__ int s_prefix;
    const unsigned FULL = 0xffffffffu;
    int i = blockIdx.x * 1024 + threadIdx.x;
    int lane = threadIdx.x & 31, wid = threadIdx.x >> 5;
    int c = (i < n) ? g_cnt[i] : 0;
    float di = rsqrtf((float)c);
    if (i < n) g_dinv[i] = di;
    int x = c;
#pragma unroll
    for (int o = 1; o < 32; o <<= 1) {
        int t = __shfl_up_sync(FULL, x, o);
        if (lane >= o) x += t;
    }
    if (lane == 31) wsum[wid] = x;
    __syncthreads();
    if (wid == 0) {
        int y = wsum[lane];
#pragma unroll
        for (int o = 1; o < 32; o <<= 1) {
            int t = __shfl_up_sync(FULL, y, o);
            if (lane >= o) y += t;
        }
        wsum[lane] = y;
    }
    __syncthreads();
    int inc = x + (wid ? wsum[wid - 1] : 0);    // inclusive within block
    if (threadIdx.x == 1023) {
        int prefix = 0;
        int b = blockIdx.x;
        if (b > 0) {
            while (g_scan_flag[b - 1] == 0) {}
            prefix = g_scan_psum[b - 1];
        }
        g_scan_psum[b] = prefix + inc;          // inc of thread1023 = block total
        __threadfence();
        g_scan_flag[b] = 1;
        s_prefix = prefix;
    }
    __syncthreads();
    int prefix = s_prefix;
    if (i < n) {
        int o = inc + prefix;
        g_off[i + 1] = o;
        int p = o - c;
        g_cur[i] = p + 1;
        g_csr_src[p] = i;
        g_csr_coef[p] = di * di;
    }
    if (i == 0) g_off[0] = 0;
}
__global__ void scatter_edges(const int* __restrict__ ei, int e) {
    int i = blockIdx.x * blockDim.x + threadIdx.x;
    if (i < e) {
        int s = ei[i];
        int d = ei[e + i];
        int p = atomicAdd(&g_cur[d], 1);
        g_csr_src[p] = s;
        g_csr_coef[p] = g_dinv[s] * g_dinv[d];
    }
}

// ---- wmma fp16 GEMM 128x128: BM=128 BN=128, 256 thr, fp32 accum -----------
// BN=0: A is fp32 (features). BN=1: A is fp16 agg output; BatchNorm+ReLU fused.
#define WS_LD 136
#define AS_LD 24
#define CS_LD 68

template <int BNA>
__global__ __launch_bounds__(256) void gemm128_wmma(
    const void* __restrict__ Av, const float* __restrict__ W,
    __half* __restrict__ C, int M,
    const float* __restrict__ gamma, const float* __restrict__ beta,
    int statsIdx, float invM) {
    __shared__ __align__(16) unsigned char smem_raw[128 * WS_LD * 2 + 128 * AS_LD * 2];
    __shared__ float coefS[128], coefT[128];
    __half* Ws = (__half*)smem_raw;
    __half* As = (__half*)(smem_raw + 128 * WS_LD * 2);
    float*  Cs = (float*)smem_raw;

    const int tid = threadIdx.x;
    const int w = tid >> 5;
    const int warprow = w >> 1;
    const int warpcol = w & 1;
    const int row0 = blockIdx.x * 128;

    if (BNA) {
        if (tid < 128) {
            float mu = g_stats[statsIdx * 256 + tid] * invM;
            float var = g_stats[statsIdx * 256 + 128 + tid] * invM - mu * mu;
            float scl = gamma[tid] * rsqrtf(var + 1e-5f);
            coefS[tid] = scl;
            coefT[tid] = beta[tid] - mu * scl;
        }
    }
    for (int i = tid; i < 2048; i += 256) {
        int base = i * 8;
        int k = base >> 7, ncol = base & 127;
        float4 f0 = *(const float4*)(W + base);
        float4 f1 = *(const float4*)(W + base + 4);
        __half2 h0 = __floats2half2_rn(f0.x, f0.y);
        __half2 h1 = __floats2half2_rn(f0.z, f0.w);
        __half2 h2 = __floats2half2_rn(f1.x, f1.y);
        __half2 h3 = __floats2half2_rn(f1.z, f1.w);
        uint4 pk;
        pk.x = *(unsigned*)&h0; pk.y = *(unsigned*)&h1;
        pk.z = *(unsigned*)&h2; pk.w = *(unsigned*)&h3;
        *(uint4*)(Ws + k * WS_LD + ncol) = pk;
    }
    __syncthreads();

    wmma::fragment<wmma::accumulator, 16, 16, 16, float> acc[2][4];
#pragma unroll
    for (int i = 0; i < 2; i++)
#pragma unroll
        for (int j = 0; j < 4; j++) wmma::fill_fragment(acc[i][j], 0.0f);

    const int arow = tid >> 1;
    const int acol = (tid & 1) << 3;

    for (int kk = 0; kk < 128; kk += 16) {
        int gr = row0 + arow;
        float f[8];
#pragma unroll
        for (int q = 0; q < 8; q++) f[q] = 0.f;
        if (gr < M) {
            if constexpr (BNA == 0) {
                const float* Af = (const float*)Av;
                float4 f0 = *(const float4*)(Af + (size_t)gr * 128 + kk + acol);
                float4 f1 = *(const float4*)(Af + (size_t)gr * 128 + kk + acol + 4);
                f[0] = f0.x; f[1] = f0.y; f[2] = f0.z; f[3] = f0.w;
                f[4] = f1.x; f[5] = f1.y; f[6] = f1.z; f[7] = f1.w;
            } else {
                const __half* Ah = (const __half*)Av;
                uint4 r = *(const uint4*)(Ah + (size_t)gr * 128 + kk + acol);
                float2 p0 = __half22float2(*(__half2*)&r.x);
                float2 p1 = __half22float2(*(__half2*)&r.y);
                float2 p2 = __half22float2(*(__half2*)&r.z);
                float2 p3 = __half22float2(*(__half2*)&r.w);
                f[0] = p0.x; f[1] = p0.y; f[2] = p1.x; f[3] = p1.y;
                f[4] = p2.x; f[5] = p2.y; f[6] = p3.x; f[7] = p3.y;
            }
        }
        if (BNA) {
            int c0 = kk + acol;
#pragma unroll
            for (int q = 0; q < 8; q++)
                f[q] = fmaxf(fmaf(f[q], coefS[c0 + q], coefT[c0 + q]), 0.f);
        }
        {
            __half2 h0 = __floats2half2_rn(f[0], f[1]);
            __half2 h1 = __floats2half2_rn(f[2], f[3]);
            __half2 h2 = __floats2half2_rn(f[4], f[5]);
            __half2 h3 = __floats2half2_rn(f[6], f[7]);
            uint4 pk;
            pk.x = *(unsigned*)&h0; pk.y = *(unsigned*)&h1;
            pk.z = *(unsigned*)&h2; pk.w = *(unsigned*)&h3;
            *(uint4*)(As + arow * AS_LD + acol) = pk;
        }
        __syncthreads();
        wmma::fragment<wmma::matrix_a, 16, 16, 16, __half, wmma::row_major> af[2];
#pragma unroll
        for (int i = 0; i < 2; i++)
            wmma::load_matrix_sync(af[i], As + (warprow * 32 + i * 16) * AS_LD, AS_LD);
#pragma unroll
        for (int j = 0; j < 4; j++) {
            wmma::fragment<wmma::matrix_b, 16, 16, 16, __half, wmma::row_major> bf;
            wmma::load_matrix_sync(bf, Ws + kk * WS_LD + warpcol * 64 + j * 16, WS_LD);
#pragma unroll
            for (int i = 0; i < 2; i++)
                wmma::mma_sync(acc[i][j], af[i], bf, acc[i][j]);
        }
        __syncthreads();
    }

#pragma unroll
    for (int r = 0; r < 2; r++) {
        if (warpcol == r) {
#pragma unroll
            for (int i = 0; i < 2; i++)
#pragma unroll
                for (int j = 0; j < 4; j++)
                    wmma::store_matrix_sync(
                        Cs + (warprow * 32 + i * 16) * CS_LD + j * 16,
                        acc[i][j], CS_LD, wmma::mem_row_major);
        }
        __syncthreads();
        int row = tid >> 1;
        int gr = row0 + row;
        if (gr < M) {
            const float* src = Cs + row * CS_LD + (tid & 1) * 32;
            __half* dst = C + (size_t)gr * 128 + r * 64 + (tid & 1) * 32;
#pragma unroll
            for (int q = 0; q < 4; q++) {
                float4 fa = ((const float4*)src)[2 * q];
                float4 fb = ((const float4*)src)[2 * q + 1];
                __half2 h0 = __floats2half2_rn(fa.x, fa.y);
                __half2 h1 = __floats2half2_rn(fa.z, fa.w);
                __half2 h2 = __floats2half2_rn(fb.x, fb.y);
                __half2 h3 = __floats2half2_rn(fb.z, fb.w);
                uint4 pk;
                pk.x = *(unsigned*)&h0; pk.y = *(unsigned*)&h1;
                pk.z = *(unsigned*)&h2; pk.w = *(unsigned*)&h3;
                ((uint4*)dst)[q] = pk;
            }
        }
        __syncthreads();
    }
}

// ------- SGEMM 128x40 from fp16 A (BN2+ReLU fused), fp16 out ---------------
__global__ void gemm40_kernel(const __half* __restrict__ A,
                              const float* __restrict__ W,
                              __half* __restrict__ C, int M,
                              const float* __restrict__ gamma,
                              const float* __restrict__ beta, float invM) {
    __shared__ float Xs[32][133];
    __shared__ float Ws[128 * 40];
    __shared__ float coefS[128], coefT[128];
    const int tid = threadIdx.x;
    const int row0 = blockIdx.x * 32;

    if (tid < 128) {
        float mu = g_stats[256 + tid] * invM;
        float var = g_stats[256 + 128 + tid] * invM - mu * mu;
        float scl = gamma[tid] * rsqrtf(var + 1e-5f);
        coefS[tid] = scl;
        coefT[tid] = beta[tid] - mu * scl;
    }
    for (int i = tid; i < 128 * 40; i += 256) Ws[i] = W[i];
    __syncthreads();
#pragma unroll
    for (int i = 0; i < 2; i++) {
        int v = tid + i * 256;            // 0..511
        int r = v >> 4, c = (v & 15) << 3;
        float f[8];
#pragma unroll
        for (int q = 0; q < 8; q++) f[q] = 0.f;
        int gr = row0 + r;
        if (gr < M) {
            uint4 rr = *(const uint4*)(A + (size_t)gr * 128 + c);
            float2 p0 = __half22float2(*(__half2*)&rr.x);
            float2 p1 = __half22float2(*(__half2*)&rr.y);
            float2 p2 = __half22float2(*(__half2*)&rr.z);
            float2 p3 = __half22float2(*(__half2*)&rr.w);
            f[0] = p0.x; f[1] = p0.y; f[2] = p1.x; f[3] = p1.y;
            f[4] = p2.x; f[5] = p2.y; f[6] = p3.x; f[7] = p3.y;
        }
#pragma unroll
        for (int q = 0; q < 8; q++)
            Xs[r][c + q] = fmaxf(fmaf(f[q], coefS[c + q], coefT[c + q]), 0.f);
    }
    __syncthreads();

    const int r = tid >> 3;
    const int cg = tid & 7;
    float acc[5] = {0.f, 0.f, 0.f, 0.f, 0.f};
#pragma unroll 8
    for (int k = 0; k < 128; k++) {
        float xv = Xs[r][k];
        const float* wr = &Ws[k * 40 + cg * 5];
#pragma unroll
        for (int c = 0; c < 5; c++) acc[c] = fmaf(xv, wr[c], acc[c]);
    }
    int gr = row0 + r;
    if (gr < M) {
        __half* outp = C + (size_t)gr * 40 + cg * 5;
#pragma unroll
        for (int c = 0; c < 5; c++) outp[c] = __float2half_rn(acc[c]);
    }
}

// ---- CSR gather agg: 16 lanes/node (2 nodes per warp), fp16 in/out, stats -
__global__ __launch_bounds__(256) void agg_csr128(
    const __half* __restrict__ H, __half* __restrict__ Agg, int n, int slot) {
    __shared__ float sh_s[128], sh_s2[128];
    if (threadIdx.x < 128) { sh_s[threadIdx.x] = 0.f; sh_s2[threadIdx.x] = 0.f; }
    __syncthreads();
    int node = (blockIdx.x * blockDim.x + threadIdx.x) >> 4;
    int sub = threadIdx.x & 15;
    if (node < n) {
        int beg = g_off[node], end = g_off[node + 1];
        float acc[8];
#pragma unroll
        for (int q = 0; q < 8; q++) acc[q] = 0.f;
        int e = beg;
        for (; e + 1 < end; e += 2) {
            int s0 = g_csr_src[e], s1 = g_csr_src[e + 1];
            float c0 = g_csr_coef[e], c1 = g_csr_coef[e + 1];
            uint4 r0 = ((const uint4*)(H + (size_t)s0 * 128))[sub];
            uint4 r1 = ((const uint4*)(H + (size_t)s1 * 128))[sub];
            float2 p;
            p = __half22float2(*(__half2*)&r0.x); acc[0] = fmaf(p.x, c0, acc[0]); acc[1] = fmaf(p.y, c0, acc[1]);
            p = __half22float2(*(__half2*)&r0.y); acc[2] = fmaf(p.x, c0, acc[2]); acc[3] = fmaf(p.y, c0, acc[3]);
            p = __half22float2(*(__half2*)&r0.z); acc[4] = fmaf(p.x, c0, acc[4]); acc[5] = fmaf(p.y, c0, acc[5]);
            p = __half22float2(*(__half2*)&r0.w); acc[6] = fmaf(p.x, c0, acc[6]); acc[7] = fmaf(p.y, c0, acc[7]);
            p = __half22float2(*(__half2*)&r1.x); acc[0] = fmaf(p.x, c1, acc[0]); acc[1] = fmaf(p.y, c1, acc[1]);
            p = __half22float2(*(__half2*)&r1.y); acc[2] = fmaf(p.x, c1, acc[2]); acc[3] = fmaf(p.y, c1, acc[3]);
            p = __half22float2(*(__half2*)&r1.z); acc[4] = fmaf(p.x, c1, acc[4]); acc[5] = fmaf(p.y, c1, acc[5]);
            p = __half22float2(*(__half2*)&r1.w); acc[6] = fmaf(p.x, c1, acc[6]); acc[7] = fmaf(p.y, c1, acc[7]);
        }
        if (e < end) {
            int s0 = g_csr_src[e];
            float c0 = g_csr_coef[e];
            uint4 r0 = ((const uint4*)(H + (size_t)s0 * 128))[sub];
            float2 p;
            p = __half22float2(*(__half2*)&r0.x); acc[0] = fmaf(p.x, c0, acc[0]); acc[1] = fmaf(p.y, c0, acc[1]);
            p = __half22float2(*(__half2*)&r0.y); acc[2] = fmaf(p.x, c0, acc[2]); acc[3] = fmaf(p.y, c0, acc[3]);
            p = __half22float2(*(__half2*)&r0.z); acc[4] = fmaf(p.x, c0, acc[4]); acc[5] = fmaf(p.y, c0, acc[5]);
            p = __half22float2(*(__half2*)&r0.w); acc[6] = fmaf(p.x, c0, acc[6]); acc[7] = fmaf(p.y, c0, acc[7]);
        }
        // fp16 store (BN stats taken from pre-rounding fp32 values)
        {
            __half2 h0 = __floats2half2_rn(acc[0], acc[1]);
            __half2 h1 = __floats2half2_rn(acc[2], acc[3]);
            __half2 h2 = __floats2half2_rn(acc[4], acc[5]);
            __half2 h3 = __floats2half2_rn(acc[6], acc[7]);
            uint4 pk;
            pk.x = *(unsigned*)&h0; pk.y = *(unsigned*)&h1;
            pk.z = *(unsigned*)&h2; pk.w = *(unsigned*)&h3;
            ((uint4*)(Agg + (size_t)node * 128))[sub] = pk;
        }
        int col = sub << 3;
#pragma unroll
        for (int q = 0; q < 8; q++) {
            atomicAdd(&sh_s[col + q], acc[q]);
            atomicAdd(&sh_s2[col + q], acc[q] * acc[q]);
        }
    }
    __syncthreads();
    if (threadIdx.x < 128) {
        atomicAdd(&g_stats[slot * 256 + threadIdx.x], sh_s[threadIdx.x]);
        atomicAdd(&g_stats[slot * 256 + 128 + threadIdx.x], sh_s2[threadIdx.x]);
    }
}

// ---- fused agg40 + bias + log-softmax: warp per node ----------------------
__global__ void agg40_logsm(const __half* __restrict__ H,
                            const float* __restrict__ b3,
                            float* __restrict__ out, int n) {
    const unsigned FULL = 0xffffffffu;
    int warp = (blockIdx.x * blockDim.x + threadIdx.x) >> 5;
    int lane = threadIdx.x & 31;
    if (warp >= n) return;
    int beg = g_off[warp], end = g_off[warp + 1];
    float4 acc = make_float4(0.f, 0.f, 0.f, 0.f);
    for (int e = beg; e < end; e++) {
        int s0 = g_csr_src[e];
        float c0 = g_csr_coef[e];
        if (lane < 10) {
            uint2 r0 = ((const uint2*)(H + (size_t)s0 * 40))[lane];
            float2 a0 = __half22float2(*(__half2*)&r0.x);
            float2 b0 = __half22float2(*(__half2*)&r0.y);
            acc.x = fmaf(a0.x, c0, acc.x);
            acc.y = fmaf(a0.y, c0, acc.y);
            acc.z = fmaf(b0.x, c0, acc.z);
            acc.w = fmaf(b0.y, c0, acc.w);
        }
    }
    float4 v = make_float4(-3.0e38f, -3.0e38f, -3.0e38f, -3.0e38f);
    if (lane < 10) {
        float4 bb = ((const float4*)b3)[lane];
        v = make_float4(acc.x + bb.x, acc.y + bb.y, acc.z + bb.z, acc.w + bb.w);
    }
    float mx = fmaxf(fmaxf(v.x, v.y), fmaxf(v.z, v.w));
#pragma unroll
    for (int o = 16; o; o >>= 1) mx = fmaxf(mx, __shfl_xor_sync(FULL, mx, o));
    float se = 0.f;
    if (lane < 10)
        se = expf(v.x - mx) + expf(v.y - mx) + expf(v.z - mx) + expf(v.w - mx);
#pragma unroll
    for (int o = 16; o; o >>= 1) se += __shfl_xor_sync(FULL, se, o);
    float sh = mx + logf(se);
    if (lane < 10)
        ((float4*)(out + (size_t)warp * 40))[lane] =
            make_float4(v.x - sh, v.y - sh, v.z - sh, v.w - sh);
}

// ---------------- launch ----------------
extern "C" void kernel_launch(void* const* d_in, const int* in_sizes, int n_in,
                              void* d_out, int out_size) {
    const float* feats = (const float*)d_in[0];
    const int*   ei    = (const int*)d_in[1];
    const float* W1 = (const float*)d_in[2];
    const float* g1 = (const float*)d_in[4];
    const float* be1 = (const float*)d_in[5];
    const float* W2 = (const float*)d_in[6];
    const float* g2 = (const float*)d_in[8];
    const float* be2 = (const float*)d_in[9];
    const float* W3 = (const float*)d_in[10];
    const float* b3 = (const float*)d_in[11];
    float* out = (float*)d_out;

    const int Nn = in_sizes[0] / HID;
    const int Ee = in_sizes[1] / 2;

    __half *hA, *hB, *h3;
    cudaGetSymbolAddress((void**)&hA, g_hA);
    cudaGetSymbolAddress((void**)&hB, g_hB);
    cudaGetSymbolAddress((void**)&h3, g_h3);

    const float invM = 1.0f / (float)Nn;
    const int nb = (Nn + 1023) / 1024;
    const int AGG16_BLOCKS = (Nn + 15) / 16;   // 16 nodes per 256-thr block
    const int AGG32_BLOCKS = (Nn + 7) / 8;

    // ---- degree + CSR build (4 kernels) ----
    deg_init<<<(Nn + 255) / 256, 256>>>(Nn);
    deg_count<<<(Ee + 255) / 256, 256>>>(ei, Ee);
    scan_fused<<<nb, 1024>>>(Nn);
    scatter_edges<<<(Ee + 255) / 256, 256>>>(ei, Ee);

    // ---- layer 1 ----
    gemm128_wmma<0><<<(Nn + 127) / 128, 256>>>(feats, W1, hA, Nn,
                                               nullptr, nullptr, 0, invM);
    agg_csr128<<<AGG16_BLOCKS, 256>>>(hA, hB, Nn, 0);

    // ---- layer 2 (BN1+ReLU fused into A-load) ----
    gemm128_wmma<1><<<(Nn + 127) / 128, 256>>>(hB, W2, hA, Nn,
                                               g1, be1, 0, invM);
    agg_csr128<<<AGG16_BLOCKS, 256>>>(hA, hB, Nn, 1);

    // ---- layer 3 (BN2+ReLU fused) ----
    gemm40_kernel<<<(Nn + 31) / 32, 256>>>(hB, W3, h3, Nn, g2, be2, invM);
    agg40_logsm<<<AGG32_BLOCKS, 256>>>(h3, b3, out, Nn);
}

// round 14
// speedup vs baseline: 1.0301x; 1.0301x over previous
#include <cuda_runtime.h>
#include <cuda_fp16.h>
#include <mma.h>
#include <math.h>

using namespace nvcuda;

#define NMAX 50000
#define EMAX 800000
#define HID  128
#define CO   40

// ---------------- scratch (device globals) ----------------
__device__ __align__(16) __half g_hA[NMAX * HID];   // gemm output (gather src)
__device__ __align__(16) __half g_hB[NMAX * HID];   // agg output (gemm A src)
__device__ __align__(16) __half g_h3[NMAX * CO];
__device__ __align__(16) float  g_dinv[NMAX];
__device__ int   g_cnt[NMAX];
__device__ int   g_off[NMAX + 1];
__device__ int   g_cur[NMAX];
__device__ int   g_csr_src[EMAX + NMAX];
__device__ float g_csr_coef[EMAX + NMAX];
__device__ __align__(16) float g_stats[2 * 256];    // slots: [sum128, sumsq128] x2
__device__ volatile int g_scan_flag[64];
__device__ volatile int g_scan_psum[64];

// ---------------- init ----------------
__global__ void deg_init(int n) {
    int i = blockIdx.x * blockDim.x + threadIdx.x;
    if (i < n) g_cnt[i] = 1;
    if (i < 512) g_stats[i] = 0.0f;
    if (i < 64) { g_scan_flag[i] = 0; g_scan_psum[i] = 0; }
}
__global__ void deg_count(const int* __restrict__ ei, int e) {
    int i = blockIdx.x * blockDim.x + threadIdx.x;
    if (i < e) atomicAdd(&g_cnt[ei[e + i]], 1);
}

// ---- fused scan: block scan + decoupled-lookback + dinv + self-scatter ----
__global__ void scan_fused(int n) {
    __shared__ int wsum[32];
    __shared__ int s_prefix;
    const unsigned FULL = 0xffffffffu;
    int i = blockIdx.x * 1024 + threadIdx.x;
    int lane = threadIdx.x & 31, wid = threadIdx.x >> 5;
    int c = (i < n) ? g_cnt[i] : 0;
    float di = rsqrtf((float)c);
    if (i < n) g_dinv[i] = di;
    int x = c;
#pragma unroll
    for (int o = 1; o < 32; o <<= 1) {
        int t = __shfl_up_sync(FULL, x, o);
        if (lane >= o) x += t;
    }
    if (lane == 31) wsum[wid] = x;
    __syncthreads();
    if (wid == 0) {
        int y = wsum[lane];
#pragma unroll
        for (int o = 1; o < 32; o <<= 1) {
            int t = __shfl_up_sync(FULL, y, o);
            if (lane >= o) y += t;
        }
        wsum[lane] = y;
    }
    __syncthreads();
    int inc = x + (wid ? wsum[wid - 1] : 0);
    if (threadIdx.x == 1023) {
        int prefix = 0;
        int b = blockIdx.x;
        if (b > 0) {
            while (g_scan_flag[b - 1] == 0) {}
            prefix = g_scan_psum[b - 1];
        }
        g_scan_psum[b] = prefix + inc;
        __threadfence();
        g_scan_flag[b] = 1;
        s_prefix = prefix;
    }
    __syncthreads();
    int prefix = s_prefix;
    if (i < n) {
        int o = inc + prefix;
        g_off[i + 1] = o;
        int p = o - c;
        g_cur[i] = p + 1;
        g_csr_src[p] = i;
        g_csr_coef[p] = di * di;
    }
    if (i == 0) g_off[0] = 0;
}
__global__ void scatter_edges(const int* __restrict__ ei, int e) {
    int i = blockIdx.x * blockDim.x + threadIdx.x;
    if (i < e) {
        int s = ei[i];
        int d = ei[e + i];
        int p = atomicAdd(&g_cur[d], 1);
        g_csr_src[p] = s;
        g_csr_coef[p] = g_dinv[s] * g_dinv[d];
    }
}

// ---- wmma fp16 GEMM 128x128 ----
#define WS_LD 136
#define AS_LD 24
#define CS_LD 68

template <int BNA>
__global__ __launch_bounds__(256) void gemm128_wmma(
    const void* __restrict__ Av, const float* __restrict__ W,
    __half* __restrict__ C, int M,
    const float* __restrict__ gamma, const float* __restrict__ beta,
    int statsIdx, float invM) {
    __shared__ __align__(16) unsigned char smem_raw[128 * WS_LD * 2 + 128 * AS_LD * 2];
    __shared__ float coefS[128], coefT[128];
    __half* Ws = (__half*)smem_raw;
    __half* As = (__half*)(smem_raw + 128 * WS_LD * 2);
    float*  Cs = (float*)smem_raw;

    const int tid = threadIdx.x;
    const int w = tid >> 5;
    const int warprow = w >> 1;
    const int warpcol = w & 1;
    const int row0 = blockIdx.x * 128;

    if (BNA) {
        if (tid < 128) {
            float mu = g_stats[statsIdx * 256 + tid] * invM;
            float var = g_stats[statsIdx * 256 + 128 + tid] * invM - mu * mu;
            float scl = gamma[tid] * rsqrtf(var + 1e-5f);
            coefS[tid] = scl;
            coefT[tid] = beta[tid] - mu * scl;
        }
    }
    for (int i = tid; i < 2048; i += 256) {
        int base = i * 8;
        int k = base >> 7, ncol = base & 127;
        float4 f0 = *(const float4*)(W + base);
        float4 f1 = *(const float4*)(W + base + 4);
        __half2 h0 = __floats2half2_rn(f0.x, f0.y);
        __half2 h1 = __floats2half2_rn(f0.z, f0.w);
        __half2 h2 = __floats2half2_rn(f1.x, f1.y);
        __half2 h3 = __floats2half2_rn(f1.z, f1.w);
        uint4 pk;
        pk.x = *(unsigned*)&h0; pk.y = *(unsigned*)&h1;
        pk.z = *(unsigned*)&h2; pk.w = *(unsigned*)&h3;
        *(uint4*)(Ws + k * WS_LD + ncol) = pk;
    }
    __syncthreads();

    wmma::fragment<wmma::accumulator, 16, 16, 16, float> acc[2][4];
#pragma unroll
    for (int i = 0; i < 2; i++)
#pragma unroll
        for (int j = 0; j < 4; j++) wmma::fill_fragment(acc[i][j], 0.0f);

    const int arow = tid >> 1;
    const int acol = (tid & 1) << 3;

    for (int kk = 0; kk < 128; kk += 16) {
        int gr = row0 + arow;
        float f[8];
#pragma unroll
        for (int q = 0; q < 8; q++) f[q] = 0.f;
        if (gr < M) {
            if constexpr (BNA == 0) {
                const float* Af = (const float*)Av;
                float4 f0 = *(const float4*)(Af + (size_t)gr * 128 + kk + acol);
                float4 f1 = *(const float4*)(Af + (size_t)gr * 128 + kk + acol + 4);
                f[0] = f0.x; f[1] = f0.y; f[2] = f0.z; f[3] = f0.w;
                f[4] = f1.x; f[5] = f1.y; f[6] = f1.z; f[7] = f1.w;
            } else {
                const __half* Ah = (const __half*)Av;
                uint4 r = *(const uint4*)(Ah + (size_t)gr * 128 + kk + acol);
                float2 p0 = __half22float2(*(__half2*)&r.x);
                float2 p1 = __half22float2(*(__half2*)&r.y);
                float2 p2 = __half22float2(*(__half2*)&r.z);
                float2 p3 = __half22float2(*(__half2*)&r.w);
                f[0] = p0.x; f[1] = p0.y; f[2] = p1.x; f[3] = p1.y;
                f[4] = p2.x; f[5] = p2.y; f[6] = p3.x; f[7] = p3.y;
            }
        }
        if (BNA) {
            int c0 = kk + acol;
#pragma unroll
            for (int q = 0; q < 8; q++)
                f[q] = fmaxf(fmaf(f[q], coefS[c0 + q], coefT[c0 + q]), 0.f);
        }
        {
            __half2 h0 = __floats2half2_rn(f[0], f[1]);
            __half2 h1 = __floats2half2_rn(f[2], f[3]);
            __half2 h2 = __floats2half2_rn(f[4], f[5]);
            __half2 h3 = __floats2half2_rn(f[6], f[7]);
            uint4 pk;
            pk.x = *(unsigned*)&h0; pk.y = *(unsigned*)&h1;
            pk.z = *(unsigned*)&h2; pk.w = *(unsigned*)&h3;
            *(uint4*)(As + arow * AS_LD + acol) = pk;
        }
        __syncthreads();
        wmma::fragment<wmma::matrix_a, 16, 16, 16, __half, wmma::row_major> af[2];
#pragma unroll
        for (int i = 0; i < 2; i++)
            wmma::load_matrix_sync(af[i], As + (warprow * 32 + i * 16) * AS_LD, AS_LD);
#pragma unroll
        for (int j = 0; j < 4; j++) {
            wmma::fragment<wmma::matrix_b, 16, 16, 16, __half, wmma::row_major> bf;
            wmma::load_matrix_sync(bf, Ws + kk * WS_LD + warpcol * 64 + j * 16, WS_LD);
#pragma unroll
            for (int i = 0; i < 2; i++)
                wmma::mma_sync(acc[i][j], af[i], bf, acc[i][j]);
        }
        __syncthreads();
    }

#pragma unroll
    for (int r = 0; r < 2; r++) {
        if (warpcol == r) {
#pragma unroll
            for (int i = 0; i < 2; i++)
#pragma unroll
                for (int j = 0; j < 4; j++)
                    wmma::store_matrix_sync(
                        Cs + (warprow * 32 + i * 16) * CS_LD + j * 16,
                        acc[i][j], CS_LD, wmma::mem_row_major);
        }
        __syncthreads();
        int row = tid >> 1;
        int gr = row0 + row;
        if (gr < M) {
            const float* src = Cs + row * CS_LD + (tid & 1) * 32;
            __half* dst = C + (size_t)gr * 128 + r * 64 + (tid & 1) * 32;
#pragma unroll
            for (int q = 0; q < 4; q++) {
                float4 fa = ((const float4*)src)[2 * q];
                float4 fb = ((const float4*)src)[2 * q + 1];
                __half2 h0 = __floats2half2_rn(fa.x, fa.y);
                __half2 h1 = __floats2half2_rn(fa.z, fa.w);
                __half2 h2 = __floats2half2_rn(fb.x, fb.y);
                __half2 h3 = __floats2half2_rn(fb.z, fb.w);
                uint4 pk;
                pk.x = *(unsigned*)&h0; pk.y = *(unsigned*)&h1;
                pk.z = *(unsigned*)&h2; pk.w = *(unsigned*)&h3;
                ((uint4*)dst)[q] = pk;
            }
        }
        __syncthreads();
    }
}

// ------- SGEMM 128x40 from fp16 A (BN2+ReLU fused), fp16 out ---------------
__global__ void gemm40_kernel(const __half* __restrict__ A,
                              const float* __restrict__ W,
                              __half* __restrict__ C, int M,
                              const float* __restrict__ gamma,
                              const float* __restrict__ beta, float invM) {
    __shared__ float Xs[32][133];
    __shared__ float Ws[128 * 40];
    __shared__ float coefS[128], coefT[128];
    const int tid = threadIdx.x;
    const int row0 = blockIdx.x * 32;

    if (tid < 128) {
        float mu = g_stats[256 + tid] * invM;
        float var = g_stats[256 + 128 + tid] * invM - mu * mu;
        float scl = gamma[tid] * rsqrtf(var + 1e-5f);
        coefS[tid] = scl;
        coefT[tid] = beta[tid] - mu * scl;
    }
    for (int i = tid; i < 128 * 40; i += 256) Ws[i] = W[i];
    __syncthreads();
#pragma unroll
    for (int i = 0; i < 2; i++) {
        int v = tid + i * 256;
        int r = v >> 4, c = (v & 15) << 3;
        float f[8];
#pragma unroll
        for (int q = 0; q < 8; q++) f[q] = 0.f;
        int gr = row0 + r;
        if (gr < M) {
            uint4 rr = *(const uint4*)(A + (size_t)gr * 128 + c);
            float2 p0 = __half22float2(*(__half2*)&rr.x);
            float2 p1 = __half22float2(*(__half2*)&rr.y);
            float2 p2 = __half22float2(*(__half2*)&rr.z);
            float2 p3 = __half22float2(*(__half2*)&rr.w);
            f[0] = p0.x; f[1] = p0.y; f[2] = p1.x; f[3] = p1.y;
            f[4] = p2.x; f[5] = p2.y; f[6] = p3.x; f[7] = p3.y;
        }
#pragma unroll
        for (int q = 0; q < 8; q++)
            Xs[r][c + q] = fmaxf(fmaf(f[q], coefS[c + q], coefT[c + q]), 0.f);
    }
    __syncthreads();

    const int r = tid >> 3;
    const int cg = tid & 7;
    float acc[5] = {0.f, 0.f, 0.f, 0.f, 0.f};
#pragma unroll 8
    for (int k = 0; k < 128; k++) {
        float xv = Xs[r][k];
        const float* wr = &Ws[k * 40 + cg * 5];
#pragma unroll
        for (int c = 0; c < 5; c++) acc[c] = fmaf(xv, wr[c], acc[c]);
    }
    int gr = row0 + r;
    if (gr < M) {
        __half* outp = C + (size_t)gr * 40 + cg * 5;
#pragma unroll
        for (int c = 0; c < 5; c++) outp[c] = __float2half_rn(acc[c]);
    }
}

// ---- CSR gather agg: warp per node, 32 lanes, fp16 in/out, fused BN stats -
__global__ __launch_bounds__(256) void agg_csr128(
    const __half* __restrict__ H, __half* __restrict__ Agg, int n, int slot) {
    __shared__ float sh_s[128], sh_s2[128];
    if (threadIdx.x < 128) { sh_s[threadIdx.x] = 0.f; sh_s2[threadIdx.x] = 0.f; }
    __syncthreads();
    int warp = (blockIdx.x * blockDim.x + threadIdx.x) >> 5;
    int lane = threadIdx.x & 31;
    float4 acc = make_float4(0.f, 0.f, 0.f, 0.f);
    bool active = (warp < n);
    if (active) {
        int beg = g_off[warp], end = g_off[warp + 1];
        int e = beg;
        for (; e + 3 < end; e += 4) {
            int   s0 = g_csr_src[e],      s1 = g_csr_src[e + 1];
            int   s2 = g_csr_src[e + 2],  s3 = g_csr_src[e + 3];
            float c0 = g_csr_coef[e],     c1 = g_csr_coef[e + 1];
            float c2 = g_csr_coef[e + 2], c3 = g_csr_coef[e + 3];
            uint2 r0 = ((const uint2*)(H + (size_t)s0 * 128))[lane];
            uint2 r1 = ((const uint2*)(H + (size_t)s1 * 128))[lane];
            uint2 r2 = ((const uint2*)(H + (size_t)s2 * 128))[lane];
            uint2 r3 = ((const uint2*)(H + (size_t)s3 * 128))[lane];
            float2 a0 = __half22float2(*(__half2*)&r0.x), b0 = __half22float2(*(__half2*)&r0.y);
            float2 a1 = __half22float2(*(__half2*)&r1.x), b1 = __half22float2(*(__half2*)&r1.y);
            float2 a2 = __half22float2(*(__half2*)&r2.x), b2 = __half22float2(*(__half2*)&r2.y);
            float2 a3 = __half22float2(*(__half2*)&r3.x), b3v = __half22float2(*(__half2*)&r3.y);
            acc.x = fmaf(a0.x, c0, fmaf(a1.x, c1, fmaf(a2.x, c2, fmaf(a3.x, c3, acc.x))));
            acc.y = fmaf(a0.y, c0, fmaf(a1.y, c1, fmaf(a2.y, c2, fmaf(a3.y, c3, acc.y))));
            acc.z = fmaf(b0.x, c0, fmaf(b1.x, c1, fmaf(b2.x, c2, fmaf(b3v.x, c3, acc.z))));
            acc.w = fmaf(b0.y, c0, fmaf(b1.y, c1, fmaf(b2.y, c2, fmaf(b3v.y, c3, acc.w))));
        }
        for (; e < end; e++) {
            int s0 = g_csr_src[e];
            float c0 = g_csr_coef[e];
            uint2 r0 = ((const uint2*)(H + (size_t)s0 * 128))[lane];
            float2 a0 = __half22float2(*(__half2*)&r0.x), b0 = __half22float2(*(__half2*)&r0.y);
            acc.x = fmaf(a0.x, c0, acc.x);
            acc.y = fmaf(a0.y, c0, acc.y);
            acc.z = fmaf(b0.x, c0, acc.z);
            acc.w = fmaf(b0.y, c0, acc.w);
        }
        // fp16 store (stats from pre-rounding fp32)
        __half2 h0 = __floats2half2_rn(acc.x, acc.y);
        __half2 h1 = __floats2half2_rn(acc.z, acc.w);
        uint2 pk;
        pk.x = *(unsigned*)&h0; pk.y = *(unsigned*)&h1;
        ((uint2*)(Agg + (size_t)warp * 128))[lane] = pk;

        int col = lane << 2;
        atomicAdd(&sh_s[col + 0], acc.x);  atomicAdd(&sh_s2[col + 0], acc.x * acc.x);
        atomicAdd(&sh_s[col + 1], acc.y);  atomicAdd(&sh_s2[col + 1], acc.y * acc.y);
        atomicAdd(&sh_s[col + 2], acc.z);  atomicAdd(&sh_s2[col + 2], acc.z * acc.z);
        atomicAdd(&sh_s[col + 3], acc.w);  atomicAdd(&sh_s2[col + 3], acc.w * acc.w);
    }
    __syncthreads();
    if (threadIdx.x < 128) {
        atomicAdd(&g_stats[slot * 256 + threadIdx.x], sh_s[threadIdx.x]);
        atomicAdd(&g_stats[slot * 256 + 128 + threadIdx.x], sh_s2[threadIdx.x]);
    }
}

// ---- fused agg40 + bias + log-softmax: warp per node ----------------------
__global__ void agg40_logsm(const __half* __restrict__ H,
                            const float* __restrict__ b3,
                            float* __restrict__ out, int n) {
    const unsigned FULL = 0xffffffffu;
    int warp = (blockIdx.x * blockDim.x + threadIdx.x) >> 5;
    int lane = threadIdx.x & 31;
    if (warp >= n) return;
    int beg = g_off[warp], end = g_off[warp + 1];
    float4 acc = make_float4(0.f, 0.f, 0.f, 0.f);
    for (int e = beg; e < end; e++) {
        int s0 = g_csr_src[e];
        float c0 = g_csr_coef[e];
        if (lane < 10) {
            uint2 r0 = ((const uint2*)(H + (size_t)s0 * 40))[lane];
            float2 a0 = __half22float2(*(__half2*)&r0.x);
            float2 b0 = __half22float2(*(__half2*)&r0.y);
            acc.x = fmaf(a0.x, c0, acc.x);
            acc.y = fmaf(a0.y, c0, acc.y);
            acc.z = fmaf(b0.x, c0, acc.z);
            acc.w = fmaf(b0.y, c0, acc.w);
        }
    }
    float4 v = make_float4(-3.0e38f, -3.0e38f, -3.0e38f, -3.0e38f);
    if (lane < 10) {
        float4 bb = ((const float4*)b3)[lane];
        v = make_float4(acc.x + bb.x, acc.y + bb.y, acc.z + bb.z, acc.w + bb.w);
    }
    float mx = fmaxf(fmaxf(v.x, v.y), fmaxf(v.z, v.w));
#pragma unroll
    for (int o = 16; o; o >>= 1) mx = fmaxf(mx, __shfl_xor_sync(FULL, mx, o));
    float se = 0.f;
    if (lane < 10)
        se = expf(v.x - mx) + expf(v.y - mx) + expf(v.z - mx) + expf(v.w - mx);
#pragma unroll
    for (int o = 16; o; o >>= 1) se += __shfl_xor_sync(FULL, se, o);
    float sh = mx + logf(se);
    if (lane < 10)
        ((float4*)(out + (size_t)warp * 40))[lane] =
            make_float4(v.x - sh, v.y - sh, v.z - sh, v.w - sh);
}

// ---------------- launch ----------------
extern "C" void kernel_launch(void* const* d_in, const int* in_sizes, int n_in,
                              void* d_out, int out_size) {
    const float* feats = (const float*)d_in[0];
    const int*   ei    = (const int*)d_in[1];
    const float* W1 = (const float*)d_in[2];
    const float* g1 = (const float*)d_in[4];
    const float* be1 = (const float*)d_in[5];
    const float* W2 = (const float*)d_in[6];
    const float* g2 = (const float*)d_in[8];
    const float* be2 = (const float*)d_in[9];
    const float* W3 = (const float*)d_in[10];
    const float* b3 = (const float*)d_in[11];
    float* out = (float*)d_out;

    const int Nn = in_sizes[0] / HID;
    const int Ee = in_sizes[1] / 2;

    __half *hA, *hB, *h3;
    cudaGetSymbolAddress((void**)&hA, g_hA);
    cudaGetSymbolAddress((void**)&hB, g_hB);
    cudaGetSymbolAddress((void**)&h3, g_h3);

    const float invM = 1.0f / (float)Nn;
    const int nb = (Nn + 1023) / 1024;
    const int AGG_BLOCKS = (Nn + 7) / 8;       // warp per node, 8 warps/block

    // ---- degree + CSR build (4 kernels) ----
    deg_init<<<(Nn + 255) / 256, 256>>>(Nn);
    deg_count<<<(Ee + 255) / 256, 256>>>(ei, Ee);
    scan_fused<<<nb, 1024>>>(Nn);
    scatter_edges<<<(Ee + 255) / 256, 256>>>(ei, Ee);

    // ---- layer 1 ----
    gemm128_wmma<0><<<(Nn + 127) / 128, 256>>>(feats, W1, hA, Nn,
                                               nullptr, nullptr, 0, invM);
    agg_csr128<<<AGG_BLOCKS, 256>>>(hA, hB, Nn, 0);

    // ---- layer 2 (BN1+ReLU fused into A-load) ----
    gemm128_wmma<1><<<(Nn + 127) / 128, 256>>>(hB, W2, hA, Nn,
                                               g1, be1, 0, invM);
    agg_csr128<<<AGG_BLOCKS, 256>>>(hA, hB, Nn, 1);

    // ---- layer 3 (BN2+ReLU fused) ----
    gemm40_kernel<<<(Nn + 31) / 32, 256>>>(hB, W3, h3, Nn, g2, be2, invM);
    agg40_logsm<<<AGG_BLOCKS, 256>>>(h3, b3, out, Nn);
}

// round 16
// speedup vs baseline: 1.4088x; 1.3676x over previous
#include <cuda_runtime.h>
#include <cuda_fp16.h>
#include <mma.h>
#include <math.h>

using namespace nvcuda;

#define NMAX 50000
#define EMAX 800000
#define HID  128
#define CO   40

// ---------------- scratch (device globals) ----------------
__device__ __align__(16) __half g_hA[NMAX * HID];   // gemm output (gather src)
__device__ __align__(16) __half g_hB[NMAX * HID];   // agg output (gemm A src)
__device__ __align__(16) __half g_h3[NMAX * CO];
__device__ __align__(16) float  g_dinv[NMAX];
__device__ int   g_cnt[NMAX];
__device__ int   g_off[NMAX + 1];
__device__ int   g_cur[NMAX];
__device__ int   g_bsum[128];
__device__ int   g_csr_src[EMAX + NMAX];
__device__ float g_csr_coef[EMAX + NMAX];
__device__ __align__(16) float g_stats[2 * 256];    // slots: [sum128, sumsq128] x2

// ---------------- init ----------------
__global__ void deg_init(int n) {
    int i = blockIdx.x * blockDim.x + threadIdx.x;
    if (i < n) g_cnt[i] = 1;
    if (i < 512) g_stats[i] = 0.0f;
}
__global__ void deg_count(const int* __restrict__ ei, int e) {
    int i = blockIdx.x * blockDim.x + threadIdx.x;
    if (i < e) atomicAdd(&g_cnt[ei[e + i]], 1);
}

// -------- scanA: block-level inclusive scan of cnt; also writes dinv -------
__global__ void scanA(int n) {
    __shared__ int wsum[32];
    const unsigned FULL = 0xffffffffu;
    int i = blockIdx.x * 1024 + threadIdx.x;
    int lane = threadIdx.x & 31, wid = threadIdx.x >> 5;
    int c = (i < n) ? g_cnt[i] : 0;
    if (i < n) g_dinv[i] = rsqrtf((float)c);
    int x = c;
#pragma unroll
    for (int o = 1; o < 32; o <<= 1) {
        int t = __shfl_up_sync(FULL, x, o);
        if (lane >= o) x += t;
    }
    if (lane == 31) wsum[wid] = x;
    __syncthreads();
    if (wid == 0) {
        int y = wsum[lane];
#pragma unroll
        for (int o = 1; o < 32; o <<= 1) {
            int t = __shfl_up_sync(FULL, y, o);
            if (lane >= o) y += t;
        }
        wsum[lane] = y;
    }
    __syncthreads();
    int inc = x + (wid ? wsum[wid - 1] : 0);
    if (i < n) g_off[i + 1] = inc;
    if (threadIdx.x == 1023) g_bsum[blockIdx.x] = inc;
}

// scanC: per-block redundant warp-scan of block sums + finalize offsets +
// cursor init + self-loop scatter (proven R11 form, no cross-block spin).
__global__ void scanC(int n, int nb) {
    __shared__ int base_s;
    const unsigned FULL = 0xffffffffu;
    if (threadIdx.x < 32) {
        int lane = threadIdx.x;
        int i0 = 2 * lane, i1 = 2 * lane + 1;
        int v0 = (i0 < nb) ? g_bsum[i0] : 0;
        int v1 = (i1 < nb) ? g_bsum[i1] : 0;
        int s = v0 + v1;
        int x = s;
#pragma unroll
        for (int o = 1; o < 32; o <<= 1) {
            int t = __shfl_up_sync(FULL, x, o);
            if (lane >= o) x += t;
        }
        int excl = x - s;
        int bid = blockIdx.x;
        if (lane == (bid >> 1))
            base_s = excl + ((bid & 1) ? v0 : 0);
    }
    __syncthreads();
    int base = base_s;
    int i = blockIdx.x * 1024 + threadIdx.x;
    if (i < n) {
        int o = g_off[i + 1] + base;
        g_off[i + 1] = o;
        int c = g_cnt[i];
        int p = o - c;
        g_cur[i] = p + 1;
        g_csr_src[p] = i;
        float di = g_dinv[i];
        g_csr_coef[p] = di * di;
    }
    if (i == 0) g_off[0] = 0;
}
__global__ void scatter_edges(const int* __restrict__ ei, int e) {
    int i = blockIdx.x * blockDim.x + threadIdx.x;
    if (i < e) {
        int s = ei[i];
        int d = ei[e + i];
        int p = atomicAdd(&g_cur[d], 1);
        g_csr_src[p] = s;
        g_csr_coef[p] = g_dinv[s] * g_dinv[d];
    }
}

// ---- wmma fp16 GEMM 128x128 ----
#define WS_LD 136
#define AS_LD 24
#define CS_LD 68

template <int BNA>
__global__ __launch_bounds__(256) void gemm128_wmma(
    const void* __restrict__ Av, const float* __restrict__ W,
    __half* __restrict__ C, int M,
    const float* __restrict__ gamma, const float* __restrict__ beta,
    int statsIdx, float invM) {
    __shared__ __align__(16) unsigned char smem_raw[128 * WS_LD * 2 + 128 * AS_LD * 2];
    __shared__ float coefS[128], coefT[128];
    __half* Ws = (__half*)smem_raw;
    __half* As = (__half*)(smem_raw + 128 * WS_LD * 2);
    float*  Cs = (float*)smem_raw;

    const int tid = threadIdx.x;
    const int w = tid >> 5;
    const int warprow = w >> 1;
    const int warpcol = w & 1;
    const int row0 = blockIdx.x * 128;

    if (BNA) {
        if (tid < 128) {
            float mu = g_stats[statsIdx * 256 + tid] * invM;
            float var = g_stats[statsIdx * 256 + 128 + tid] * invM - mu * mu;
            float scl = gamma[tid] * rsqrtf(var + 1e-5f);
            coefS[tid] = scl;
            coefT[tid] = beta[tid] - mu * scl;
        }
    }
    for (int i = tid; i < 2048; i += 256) {
        int base = i * 8;
        int k = base >> 7, ncol = base & 127;
        float4 f0 = *(const float4*)(W + base);
        float4 f1 = *(const float4*)(W + base + 4);
        __half2 h0 = __floats2half2_rn(f0.x, f0.y);
        __half2 h1 = __floats2half2_rn(f0.z, f0.w);
        __half2 h2 = __floats2half2_rn(f1.x, f1.y);
        __half2 h3 = __floats2half2_rn(f1.z, f1.w);
        uint4 pk;
        pk.x = *(unsigned*)&h0; pk.y = *(unsigned*)&h1;
        pk.z = *(unsigned*)&h2; pk.w = *(unsigned*)&h3;
        *(uint4*)(Ws + k * WS_LD + ncol) = pk;
    }
    __syncthreads();

    wmma::fragment<wmma::accumulator, 16, 16, 16, float> acc[2][4];
#pragma unroll
    for (int i = 0; i < 2; i++)
#pragma unroll
        for (int j = 0; j < 4; j++) wmma::fill_fragment(acc[i][j], 0.0f);

    const int arow = tid >> 1;
    const int acol = (tid & 1) << 3;

    for (int kk = 0; kk < 128; kk += 16) {
        int gr = row0 + arow;
        float f[8];
#pragma unroll
        for (int q = 0; q < 8; q++) f[q] = 0.f;
        if (gr < M) {
            if constexpr (BNA == 0) {
                const float* Af = (const float*)Av;
                float4 f0 = *(const float4*)(Af + (size_t)gr * 128 + kk + acol);
                float4 f1 = *(const float4*)(Af + (size_t)gr * 128 + kk + acol + 4);
                f[0] = f0.x; f[1] = f0.y; f[2] = f0.z; f[3] = f0.w;
                f[4] = f1.x; f[5] = f1.y; f[6] = f1.z; f[7] = f1.w;
            } else {
                const __half* Ah = (const __half*)Av;
                uint4 r = *(const uint4*)(Ah + (size_t)gr * 128 + kk + acol);
                float2 p0 = __half22float2(*(__half2*)&r.x);
                float2 p1 = __half22float2(*(__half2*)&r.y);
                float2 p2 = __half22float2(*(__half2*)&r.z);
                float2 p3 = __half22float2(*(__half2*)&r.w);
                f[0] = p0.x; f[1] = p0.y; f[2] = p1.x; f[3] = p1.y;
                f[4] = p2.x; f[5] = p2.y; f[6] = p3.x; f[7] = p3.y;
            }
        }
        if (BNA) {
            int c0 = kk + acol;
#pragma unroll
            for (int q = 0; q < 8; q++)
                f[q] = fmaxf(fmaf(f[q], coefS[c0 + q], coefT[c0 + q]), 0.f);
        }
        {
            __half2 h0 = __floats2half2_rn(f[0], f[1]);
            __half2 h1 = __floats2half2_rn(f[2], f[3]);
            __half2 h2 = __floats2half2_rn(f[4], f[5]);
            __half2 h3 = __floats2half2_rn(f[6], f[7]);
            uint4 pk;
            pk.x = *(unsigned*)&h0; pk.y = *(unsigned*)&h1;
            pk.z = *(unsigned*)&h2; pk.w = *(unsigned*)&h3;
            *(uint4*)(As + arow * AS_LD + acol) = pk;
        }
        __syncthreads();
        wmma::fragment<wmma::matrix_a, 16, 16, 16, __half, wmma::row_major> af[2];
#pragma unroll
        for (int i = 0; i < 2; i++)
            wmma::load_matrix_sync(af[i], As + (warprow * 32 + i * 16) * AS_LD, AS_LD);
#pragma unroll
        for (int j = 0; j < 4; j++) {
            wmma::fragment<wmma::matrix_b, 16, 16, 16, __half, wmma::row_major> bf;
            wmma::load_matrix_sync(bf, Ws + kk * WS_LD + warpcol * 64 + j * 16, WS_LD);
#pragma unroll
            for (int i = 0; i < 2; i++)
                wmma::mma_sync(acc[i][j], af[i], bf, acc[i][j]);
        }
        __syncthreads();
    }

#pragma unroll
    for (int r = 0; r < 2; r++) {
        if (warpcol == r) {
#pragma unroll
            for (int i = 0; i < 2; i++)
#pragma unroll
                for (int j = 0; j < 4; j++)
                    wmma::store_matrix_sync(
                        Cs + (warprow * 32 + i * 16) * CS_LD + j * 16,
                        acc[i][j], CS_LD, wmma::mem_row_major);
        }
        __syncthreads();
        int row = tid >> 1;
        int gr = row0 + row;
        if (gr < M) {
            const float* src = Cs + row * CS_LD + (tid & 1) * 32;
            __half* dst = C + (size_t)gr * 128 + r * 64 + (tid & 1) * 32;
#pragma unroll
            for (int q = 0; q < 4; q++) {
                float4 fa = ((const float4*)src)[2 * q];
                float4 fb = ((const float4*)src)[2 * q + 1];
                __half2 h0 = __floats2half2_rn(fa.x, fa.y);
                __half2 h1 = __floats2half2_rn(fa.z, fa.w);
                __half2 h2 = __floats2half2_rn(fb.x, fb.y);
                __half2 h3 = __floats2half2_rn(fb.z, fb.w);
                uint4 pk;
                pk.x = *(unsigned*)&h0; pk.y = *(unsigned*)&h1;
                pk.z = *(unsigned*)&h2; pk.w = *(unsigned*)&h3;
                ((uint4*)dst)[q] = pk;
            }
        }
        __syncthreads();
    }
}

// ------- SGEMM 128x40 from fp16 A (BN2+ReLU fused), fp16 out ---------------
__global__ void gemm40_kernel(const __half* __restrict__ A,
                              const float* __restrict__ W,
                              __half* __restrict__ C, int M,
                              const float* __restrict__ gamma,
                              const float* __restrict__ beta, float invM) {
    __shared__ float Xs[32][133];
    __shared__ float Ws[128 * 40];
    __shared__ float coefS[128], coefT[128];
    const int tid = threadIdx.x;
    const int row0 = blockIdx.x * 32;

    if (tid < 128) {
        float mu = g_stats[256 + tid] * invM;
        float var = g_stats[256 + 128 + tid] * invM - mu * mu;
        float scl = gamma[tid] * rsqrtf(var + 1e-5f);
        coefS[tid] = scl;
        coefT[tid] = beta[tid] - mu * scl;
    }
    for (int i = tid; i < 128 * 40; i += 256) Ws[i] = W[i];
    __syncthreads();
#pragma unroll
    for (int i = 0; i < 2; i++) {
        int v = tid + i * 256;
        int r = v >> 4, c = (v & 15) << 3;
        float f[8];
#pragma unroll
        for (int q = 0; q < 8; q++) f[q] = 0.f;
        int gr = row0 + r;
        if (gr < M) {
            uint4 rr = *(const uint4*)(A + (size_t)gr * 128 + c);
            float2 p0 = __half22float2(*(__half2*)&rr.x);
            float2 p1 = __half22float2(*(__half2*)&rr.y);
            float2 p2 = __half22float2(*(__half2*)&rr.z);
            float2 p3 = __half22float2(*(__half2*)&rr.w);
            f[0] = p0.x; f[1] = p0.y; f[2] = p1.x; f[3] = p1.y;
            f[4] = p2.x; f[5] = p2.y; f[6] = p3.x; f[7] = p3.y;
        }
#pragma unroll
        for (int q = 0; q < 8; q++)
            Xs[r][c + q] = fmaxf(fmaf(f[q], coefS[c + q], coefT[c + q]), 0.f);
    }
    __syncthreads();

    const int r = tid >> 3;
    const int cg = tid & 7;
    float acc[5] = {0.f, 0.f, 0.f, 0.f, 0.f};
#pragma unroll 8
    for (int k = 0; k < 128; k++) {
        float xv = Xs[r][k];
        const float* wr = &Ws[k * 40 + cg * 5];
#pragma unroll
        for (int c = 0; c < 5; c++) acc[c] = fmaf(xv, wr[c], acc[c]);
    }
    int gr = row0 + r;
    if (gr < M) {
        __half* outp = C + (size_t)gr * 40 + cg * 5;
#pragma unroll
        for (int c = 0; c < 5; c++) outp[c] = __float2half_rn(acc[c]);
    }
}

// ---- CSR gather agg: warp per node, 32 lanes, fp16 in/out, fused BN stats -
__global__ __launch_bounds__(256) void agg_csr128(
    const __half* __restrict__ H, __half* __restrict__ Agg, int n, int slot) {
    __shared__ float sh_s[128], sh_s2[128];
    if (threadIdx.x < 128) { sh_s[threadIdx.x] = 0.f; sh_s2[threadIdx.x] = 0.f; }
    __syncthreads();
    int warp = (blockIdx.x * blockDim.x + threadIdx.x) >> 5;
    int lane = threadIdx.x & 31;
    float4 acc = make_float4(0.f, 0.f, 0.f, 0.f);
    bool active = (warp < n);
    if (active) {
        int beg = g_off[warp], end = g_off[warp + 1];
        int e = beg;
        for (; e + 3 < end; e += 4) {
            int   s0 = g_csr_src[e],      s1 = g_csr_src[e + 1];
            int   s2 = g_csr_src[e + 2],  s3 = g_csr_src[e + 3];
            float c0 = g_csr_coef[e],     c1 = g_csr_coef[e + 1];
            float c2 = g_csr_coef[e + 2], c3 = g_csr_coef[e + 3];
            uint2 r0 = ((const uint2*)(H + (size_t)s0 * 128))[lane];
            uint2 r1 = ((const uint2*)(H + (size_t)s1 * 128))[lane];
            uint2 r2 = ((const uint2*)(H + (size_t)s2 * 128))[lane];
            uint2 r3 = ((const uint2*)(H + (size_t)s3 * 128))[lane];
            float2 a0 = __half22float2(*(__half2*)&r0.x), b0 = __half22float2(*(__half2*)&r0.y);
            float2 a1 = __half22float2(*(__half2*)&r1.x), b1 = __half22float2(*(__half2*)&r1.y);
            float2 a2 = __half22float2(*(__half2*)&r2.x), b2 = __half22float2(*(__half2*)&r2.y);
            float2 a3 = __half22float2(*(__half2*)&r3.x), b3v = __half22float2(*(__half2*)&r3.y);
            acc.x = fmaf(a0.x, c0, fmaf(a1.x, c1, fmaf(a2.x, c2, fmaf(a3.x, c3, acc.x))));
            acc.y = fmaf(a0.y, c0, fmaf(a1.y, c1, fmaf(a2.y, c2, fmaf(a3.y, c3, acc.y))));
            acc.z = fmaf(b0.x, c0, fmaf(b1.x, c1, fmaf(b2.x, c2, fmaf(b3v.x, c3, acc.z))));
            acc.w = fmaf(b0.y, c0, fmaf(b1.y, c1, fmaf(b2.y, c2, fmaf(b3v.y, c3, acc.w))));
        }
        for (; e < end; e++) {
            int s0 = g_csr_src[e];
            float c0 = g_csr_coef[e];
            uint2 r0 = ((const uint2*)(H + (size_t)s0 * 128))[lane];
            float2 a0 = __half22float2(*(__half2*)&r0.x), b0 = __half22float2(*(__half2*)&r0.y);
            acc.x = fmaf(a0.x, c0, acc.x);
            acc.y = fmaf(a0.y, c0, acc.y);
            acc.z = fmaf(b0.x, c0, acc.z);
            acc.w = fmaf(b0.y, c0, acc.w);
        }
        // fp16 store (stats from pre-rounding fp32)
        __half2 h0 = __floats2half2_rn(acc.x, acc.y);
        __half2 h1 = __floats2half2_rn(acc.z, acc.w);
        uint2 pk;
        pk.x = *(unsigned*)&h0; pk.y = *(unsigned*)&h1;
        ((uint2*)(Agg + (size_t)warp * 128))[lane] = pk;

        int col = lane << 2;
        atomicAdd(&sh_s[col + 0], acc.x);  atomicAdd(&sh_s2[col + 0], acc.x * acc.x);
        atomicAdd(&sh_s[col + 1], acc.y);  atomicAdd(&sh_s2[col + 1], acc.y * acc.y);
        atomicAdd(&sh_s[col + 2], acc.z);  atomicAdd(&sh_s2[col + 2], acc.z * acc.z);
        atomicAdd(&sh_s[col + 3], acc.w);  atomicAdd(&sh_s2[col + 3], acc.w * acc.w);
    }
    __syncthreads();
    if (threadIdx.x < 128) {
        atomicAdd(&g_stats[slot * 256 + threadIdx.x], sh_s[threadIdx.x]);
        atomicAdd(&g_stats[slot * 256 + 128 + threadIdx.x], sh_s2[threadIdx.x]);
    }
}

// ---- fused agg40 + bias + log-softmax: warp per node ----------------------
__global__ void agg40_logsm(const __half* __restrict__ H,
                            const float* __restrict__ b3,
                            float* __restrict__ out, int n) {
    const unsigned FULL = 0xffffffffu;
    int warp = (blockIdx.x * blockDim.x + threadIdx.x) >> 5;
    int lane = threadIdx.x & 31;
    if (warp >= n) return;
    int beg = g_off[warp], end = g_off[warp + 1];
    float4 acc = make_float4(0.f, 0.f, 0.f, 0.f);
    for (int e = beg; e < end; e++) {
        int s0 = g_csr_src[e];
        float c0 = g_csr_coef[e];
        if (lane < 10) {
            uint2 r0 = ((const uint2*)(H + (size_t)s0 * 40))[lane];
            float2 a0 = __half22float2(*(__half2*)&r0.x);
            float2 b0 = __half22float2(*(__half2*)&r0.y);
            acc.x = fmaf(a0.x, c0, acc.x);
            acc.y = fmaf(a0.y, c0, acc.y);
            acc.z = fmaf(b0.x, c0, acc.z);
            acc.w = fmaf(b0.y, c0, acc.w);
        }
    }
    float4 v = make_float4(-3.0e38f, -3.0e38f, -3.0e38f, -3.0e38f);
    if (lane < 10) {
        float4 bb = ((const float4*)b3)[lane];
        v = make_float4(acc.x + bb.x, acc.y + bb.y, acc.z + bb.z, acc.w + bb.w);
    }
    float mx = fmaxf(fmaxf(v.x, v.y), fmaxf(v.z, v.w));
#pragma unroll
    for (int o = 16; o; o >>= 1) mx = fmaxf(mx, __shfl_xor_sync(FULL, mx, o));
    float se = 0.f;
    if (lane < 10)
        se = expf(v.x - mx) + expf(v.y - mx) + expf(v.z - mx) + expf(v.w - mx);
#pragma unroll
    for (int o = 16; o; o >>= 1) se += __shfl_xor_sync(FULL, se, o);
    float sh = mx + logf(se);
    if (lane < 10)
        ((float4*)(out + (size_t)warp * 40))[lane] =
            make_float4(v.x - sh, v.y - sh, v.z - sh, v.w - sh);
}

// ---------------- launch ----------------
extern "C" void kernel_launch(void* const* d_in, const int* in_sizes, int n_in,
                              void* d_out, int out_size) {
    const float* feats = (const float*)d_in[0];
    const int*   ei    = (const int*)d_in[1];
    const float* W1 = (const float*)d_in[2];
    const float* g1 = (const float*)d_in[4];
    const float* be1 = (const float*)d_in[5];
    const float* W2 = (const float*)d_in[6];
    const float* g2 = (const float*)d_in[8];
    const float* be2 = (const float*)d_in[9];
    const float* W3 = (const float*)d_in[10];
    const float* b3 = (const float*)d_in[11];
    float* out = (float*)d_out;

    const int Nn = in_sizes[0] / HID;
    const int Ee = in_sizes[1] / 2;

    __half *hA, *hB, *h3;
    cudaGetSymbolAddress((void**)&hA, g_hA);
    cudaGetSymbolAddress((void**)&hB, g_hB);
    cudaGetSymbolAddress((void**)&h3, g_h3);

    const float invM = 1.0f / (float)Nn;
    const int nb = (Nn + 1023) / 1024;
    const int AGG_BLOCKS = (Nn + 7) / 8;       // warp per node, 8 warps/block

    // ---- degree + CSR build (5 kernels, R11-proven scan) ----
    deg_init<<<(Nn + 255) / 256, 256>>>(Nn);
    deg_count<<<(Ee + 255) / 256, 256>>>(ei, Ee);
    scanA<<<nb, 1024>>>(Nn);
    scanC<<<nb, 1024>>>(Nn, nb);
    scatter_edges<<<(Ee + 255) / 256, 256>>>(ei, Ee);

    // ---- layer 1 ----
    gemm128_wmma<0><<<(Nn + 127) / 128, 256>>>(feats, W1, hA, Nn,
                                               nullptr, nullptr, 0, invM);
    agg_csr128<<<AGG_BLOCKS, 256>>>(hA, hB, Nn, 0);

    // ---- layer 2 (BN1+ReLU fused into A-load) ----
    gemm128_wmma<1><<<(Nn + 127) / 128, 256>>>(hB, W2, hA, Nn,
                                               g1, be1, 0, invM);
    agg_csr128<<<AGG_BLOCKS, 256>>>(hA, hB, Nn, 1);

    // ---- layer 3 (BN2+ReLU fused) ----
    gemm40_kernel<<<(Nn + 31) / 32, 256>>>(hB, W3, h3, Nn, g2, be2, invM);
    agg40_logsm<<<AGG_BLOCKS, 256>>>(h3, b3, out, Nn);
}

// round 17
// speedup vs baseline: 1.4296x; 1.0147x over previous
#include <cuda_runtime.h>
#include <cuda_fp16.h>
#include <mma.h>
#include <math.h>

using namespace nvcuda;

#define NMAX 50000
#define EMAX 800000
#define HID  128
#define CO   40

// ---------------- scratch (device globals) ----------------
__device__ __align__(16) __half g_hA[NMAX * HID];   // gemm output (gather src)
__device__ __align__(16) __half g_hB[NMAX * HID];   // agg output (gemm A src)
__device__ __align__(16) __half g_h3[NMAX * CO];
__device__ __align__(16) float  g_dinv[NMAX];
__device__ int   g_cnt[NMAX];
__device__ int   g_off[NMAX + 1];
__device__ int   g_cur[NMAX];
__device__ int   g_bsum[128];
__device__ __align__(16) int2 g_csr[EMAX + NMAX];   // (src, coef-as-int) packed
__device__ __align__(16) float g_stats[2 * 256];    // slots: [sum128, sumsq128] x2

// ---------------- init ----------------
__global__ void deg_init(int n) {
    int i = blockIdx.x * blockDim.x + threadIdx.x;
    if (i < n) g_cnt[i] = 1;
    if (i < 512) g_stats[i] = 0.0f;
}
__global__ void deg_count(const int* __restrict__ ei, int e) {
    int i = blockIdx.x * blockDim.x + threadIdx.x;
    if (i < e) atomicAdd(&g_cnt[ei[e + i]], 1);
}

// -------- scanA: block-level inclusive scan of cnt; also writes dinv -------
__global__ void scanA(int n) {
    __shared__ int wsum[32];
    const unsigned FULL = 0xffffffffu;
    int i = blockIdx.x * 1024 + threadIdx.x;
    int lane = threadIdx.x & 31, wid = threadIdx.x >> 5;
    int c = (i < n) ? g_cnt[i] : 0;
    if (i < n) g_dinv[i] = rsqrtf((float)c);
    int x = c;
#pragma unroll
    for (int o = 1; o < 32; o <<= 1) {
        int t = __shfl_up_sync(FULL, x, o);
        if (lane >= o) x += t;
    }
    if (lane == 31) wsum[wid] = x;
    __syncthreads();
    if (wid == 0) {
        int y = wsum[lane];
#pragma unroll
        for (int o = 1; o < 32; o <<= 1) {
            int t = __shfl_up_sync(FULL, y, o);
            if (lane >= o) y += t;
        }
        wsum[lane] = y;
    }
    __syncthreads();
    int inc = x + (wid ? wsum[wid - 1] : 0);
    if (i < n) g_off[i + 1] = inc;
    if (threadIdx.x == 1023) g_bsum[blockIdx.x] = inc;
}

// scanC: per-block redundant warp-scan of block sums + finalize offsets +
// cursor init + self-loop scatter.
__global__ void scanC(int n, int nb) {
    __shared__ int base_s;
    const unsigned FULL = 0xffffffffu;
    if (threadIdx.x < 32) {
        int lane = threadIdx.x;
        int i0 = 2 * lane, i1 = 2 * lane + 1;
        int v0 = (i0 < nb) ? g_bsum[i0] : 0;
        int v1 = (i1 < nb) ? g_bsum[i1] : 0;
        int s = v0 + v1;
        int x = s;
#pragma unroll
        for (int o = 1; o < 32; o <<= 1) {
            int t = __shfl_up_sync(FULL, x, o);
            if (lane >= o) x += t;
        }
        int excl = x - s;
        int bid = blockIdx.x;
        if (lane == (bid >> 1))
            base_s = excl + ((bid & 1) ? v0 : 0);
    }
    __syncthreads();
    int base = base_s;
    int i = blockIdx.x * 1024 + threadIdx.x;
    if (i < n) {
        int o = g_off[i + 1] + base;
        g_off[i + 1] = o;
        int c = g_cnt[i];
        int p = o - c;
        g_cur[i] = p + 1;
        float di = g_dinv[i];
        g_csr[p] = make_int2(i, __float_as_int(di * di));
    }
    if (i == 0) g_off[0] = 0;
}
__global__ void scatter_edges(const int* __restrict__ ei, int e) {
    int i = blockIdx.x * blockDim.x + threadIdx.x;
    if (i < e) {
        int s = ei[i];
        int d = ei[e + i];
        int p = atomicAdd(&g_cur[d], 1);
        g_csr[p] = make_int2(s, __float_as_int(g_dinv[s] * g_dinv[d]));
    }
}

// ---- wmma fp16 GEMM 128x128 ----
#define WS_LD 136
#define AS_LD 24
#define CS_LD 68

template <int BNA>
__global__ __launch_bounds__(256) void gemm128_wmma(
    const void* __restrict__ Av, const float* __restrict__ W,
    __half* __restrict__ C, int M,
    const float* __restrict__ gamma, const float* __restrict__ beta,
    int statsIdx, float invM) {
    __shared__ __align__(16) unsigned char smem_raw[128 * WS_LD * 2 + 128 * AS_LD * 2];
    __shared__ float coefS[128], coefT[128];
    __half* Ws = (__half*)smem_raw;
    __half* As = (__half*)(smem_raw + 128 * WS_LD * 2);
    float*  Cs = (float*)smem_raw;

    const int tid = threadIdx.x;
    const int w = tid >> 5;
    const int warprow = w >> 1;
    const int warpcol = w & 1;
    const int row0 = blockIdx.x * 128;

    if (BNA) {
        if (tid < 128) {
            float mu = g_stats[statsIdx * 256 + tid] * invM;
            float var = g_stats[statsIdx * 256 + 128 + tid] * invM - mu * mu;
            float scl = gamma[tid] * rsqrtf(var + 1e-5f);
            coefS[tid] = scl;
            coefT[tid] = beta[tid] - mu * scl;
        }
    }
    for (int i = tid; i < 2048; i += 256) {
        int base = i * 8;
        int k = base >> 7, ncol = base & 127;
        float4 f0 = *(const float4*)(W + base);
        float4 f1 = *(const float4*)(W + base + 4);
        __half2 h0 = __floats2half2_rn(f0.x, f0.y);
        __half2 h1 = __floats2half2_rn(f0.z, f0.w);
        __half2 h2 = __floats2half2_rn(f1.x, f1.y);
        __half2 h3 = __floats2half2_rn(f1.z, f1.w);
        uint4 pk;
        pk.x = *(unsigned*)&h0; pk.y = *(unsigned*)&h1;
        pk.z = *(unsigned*)&h2; pk.w = *(unsigned*)&h3;
        *(uint4*)(Ws + k * WS_LD + ncol) = pk;
    }
    __syncthreads();

    wmma::fragment<wmma::accumulator, 16, 16, 16, float> acc[2][4];
#pragma unroll
    for (int i = 0; i < 2; i++)
#pragma unroll
        for (int j = 0; j < 4; j++) wmma::fill_fragment(acc[i][j], 0.0f);

    const int arow = tid >> 1;
    const int acol = (tid & 1) << 3;

    for (int kk = 0; kk < 128; kk += 16) {
        int gr = row0 + arow;
        float f[8];
#pragma unroll
        for (int q = 0; q < 8; q++) f[q] = 0.f;
        if (gr < M) {
            if constexpr (BNA == 0) {
                const float* Af = (const float*)Av;
                float4 f0 = *(const float4*)(Af + (size_t)gr * 128 + kk + acol);
                float4 f1 = *(const float4*)(Af + (size_t)gr * 128 + kk + acol + 4);
                f[0] = f0.x; f[1] = f0.y; f[2] = f0.z; f[3] = f0.w;
                f[4] = f1.x; f[5] = f1.y; f[6] = f1.z; f[7] = f1.w;
            } else {
                const __half* Ah = (const __half*)Av;
                uint4 r = *(const uint4*)(Ah + (size_t)gr * 128 + kk + acol);
                float2 p0 = __half22float2(*(__half2*)&r.x);
                float2 p1 = __half22float2(*(__half2*)&r.y);
                float2 p2 = __half22float2(*(__half2*)&r.z);
                float2 p3 = __half22float2(*(__half2*)&r.w);
                f[0] = p0.x; f[1] = p0.y; f[2] = p1.x; f[3] = p1.y;
                f[4] = p2.x; f[5] = p2.y; f[6] = p3.x; f[7] = p3.y;
            }
        }
        if (BNA) {
            int c0 = kk + acol;
#pragma unroll
            for (int q = 0; q < 8; q++)
                f[q] = fmaxf(fmaf(f[q], coefS[c0 + q], coefT[c0 + q]), 0.f);
        }
        {
            __half2 h0 = __floats2half2_rn(f[0], f[1]);
            __half2 h1 = __floats2half2_rn(f[2], f[3]);
            __half2 h2 = __floats2half2_rn(f[4], f[5]);
            __half2 h3 = __floats2half2_rn(f[6], f[7]);
            uint4 pk;
            pk.x = *(unsigned*)&h0; pk.y = *(unsigned*)&h1;
            pk.z = *(unsigned*)&h2; pk.w = *(unsigned*)&h3;
            *(uint4*)(As + arow * AS_LD + acol) = pk;
        }
        __syncthreads();
        wmma::fragment<wmma::matrix_a, 16, 16, 16, __half, wmma::row_major> af[2];
#pragma unroll
        for (int i = 0; i < 2; i++)
            wmma::load_matrix_sync(af[i], As + (warprow * 32 + i * 16) * AS_LD, AS_LD);
#pragma unroll
        for (int j = 0; j < 4; j++) {
            wmma::fragment<wmma::matrix_b, 16, 16, 16, __half, wmma::row_major> bf;
            wmma::load_matrix_sync(bf, Ws + kk * WS_LD + warpcol * 64 + j * 16, WS_LD);
#pragma unroll
            for (int i = 0; i < 2; i++)
                wmma::mma_sync(acc[i][j], af[i], bf, acc[i][j]);
        }
        __syncthreads();
    }

#pragma unroll
    for (int r = 0; r < 2; r++) {
        if (warpcol == r) {
#pragma unroll
            for (int i = 0; i < 2; i++)
#pragma unroll
                for (int j = 0; j < 4; j++)
                    wmma::store_matrix_sync(
                        Cs + (warprow * 32 + i * 16) * CS_LD + j * 16,
                        acc[i][j], CS_LD, wmma::mem_row_major);
        }
        __syncthreads();
        int row = tid >> 1;
        int gr = row0 + row;
        if (gr < M) {
            const float* src = Cs + row * CS_LD + (tid & 1) * 32;
            __half* dst = C + (size_t)gr * 128 + r * 64 + (tid & 1) * 32;
#pragma unroll
            for (int q = 0; q < 4; q++) {
                float4 fa = ((const float4*)src)[2 * q];
                float4 fb = ((const float4*)src)[2 * q + 1];
                __half2 h0 = __floats2half2_rn(fa.x, fa.y);
                __half2 h1 = __floats2half2_rn(fa.z, fa.w);
                __half2 h2 = __floats2half2_rn(fb.x, fb.y);
                __half2 h3 = __floats2half2_rn(fb.z, fb.w);
                uint4 pk;
                pk.x = *(unsigned*)&h0; pk.y = *(unsigned*)&h1;
                pk.z = *(unsigned*)&h2; pk.w = *(unsigned*)&h3;
                ((uint4*)dst)[q] = pk;
            }
        }
        __syncthreads();
    }
}

// ------- SGEMM 128x40 from fp16 A (BN2+ReLU fused), fp16 out ---------------
__global__ void gemm40_kernel(const __half* __restrict__ A,
                              const float* __restrict__ W,
                              __half* __restrict__ C, int M,
                              const float* __restrict__ gamma,
                              const float* __restrict__ beta, float invM) {
    __shared__ float Xs[32][133];
    __shared__ float Ws[128 * 40];
    __shared__ float coefS[128], coefT[128];
    const int tid = threadIdx.x;
    const int row0 = blockIdx.x * 32;

    if (tid < 128) {
        float mu = g_stats[256 + tid] * invM;
        float var = g_stats[256 + 128 + tid] * invM - mu * mu;
        float scl = gamma[tid] * rsqrtf(var + 1e-5f);
        coefS[tid] = scl;
        coefT[tid] = beta[tid] - mu * scl;
    }
    for (int i = tid; i < 128 * 40; i += 256) Ws[i] = W[i];
    __syncthreads();
#pragma unroll
    for (int i = 0; i < 2; i++) {
        int v = tid + i * 256;
        int r = v >> 4, c = (v & 15) << 3;
        float f[8];
#pragma unroll
        for (int q = 0; q < 8; q++) f[q] = 0.f;
        int gr = row0 + r;
        if (gr < M) {
            uint4 rr = *(const uint4*)(A + (size_t)gr * 128 + c);
            float2 p0 = __half22float2(*(__half2*)&rr.x);
            float2 p1 = __half22float2(*(__half2*)&rr.y);
            float2 p2 = __half22float2(*(__half2*)&rr.z);
            float2 p3 = __half22float2(*(__half2*)&rr.w);
            f[0] = p0.x; f[1] = p0.y; f[2] = p1.x; f[3] = p1.y;
            f[4] = p2.x; f[5] = p2.y; f[6] = p3.x; f[7] = p3.y;
        }
#pragma unroll
        for (int q = 0; q < 8; q++)
            Xs[r][c + q] = fmaxf(fmaf(f[q], coefS[c + q], coefT[c + q]), 0.f);
    }
    __syncthreads();

    const int r = tid >> 3;
    const int cg = tid & 7;
    float acc[5] = {0.f, 0.f, 0.f, 0.f, 0.f};
#pragma unroll 8
    for (int k = 0; k < 128; k++) {
        float xv = Xs[r][k];
        const float* wr = &Ws[k * 40 + cg * 5];
#pragma unroll
        for (int c = 0; c < 5; c++) acc[c] = fmaf(xv, wr[c], acc[c]);
    }
    int gr = row0 + r;
    if (gr < M) {
        __half* outp = C + (size_t)gr * 40 + cg * 5;
#pragma unroll
        for (int c = 0; c < 5; c++) outp[c] = __float2half_rn(acc[c]);
    }
}

// ---- CSR gather agg: warp per node, fp16 in/out, packed (src,coef), x8 ----
__global__ __launch_bounds__(256) void agg_csr128(
    const __half* __restrict__ H, __half* __restrict__ Agg, int n, int slot) {
    __shared__ float sh_s[128], sh_s2[128];
    if (threadIdx.x < 128) { sh_s[threadIdx.x] = 0.f; sh_s2[threadIdx.x] = 0.f; }
    __syncthreads();
    int warp = (blockIdx.x * blockDim.x + threadIdx.x) >> 5;
    int lane = threadIdx.x & 31;
    float4 acc = make_float4(0.f, 0.f, 0.f, 0.f);
    bool active = (warp < n);
    if (active) {
        int beg = g_off[warp], end = g_off[warp + 1];
        int e = beg;
        for (; e + 7 < end; e += 8) {
            int2 p0 = g_csr[e],     p1 = g_csr[e + 1];
            int2 p2 = g_csr[e + 2], p3 = g_csr[e + 3];
            int2 p4 = g_csr[e + 4], p5 = g_csr[e + 5];
            int2 p6 = g_csr[e + 6], p7 = g_csr[e + 7];
            uint2 r0 = ((const uint2*)(H + (size_t)p0.x * 128))[lane];
            uint2 r1 = ((const uint2*)(H + (size_t)p1.x * 128))[lane];
            uint2 r2 = ((const uint2*)(H + (size_t)p2.x * 128))[lane];
            uint2 r3 = ((const uint2*)(H + (size_t)p3.x * 128))[lane];
            uint2 r4 = ((const uint2*)(H + (size_t)p4.x * 128))[lane];
            uint2 r5 = ((const uint2*)(H + (size_t)p5.x * 128))[lane];
            uint2 r6 = ((const uint2*)(H + (size_t)p6.x * 128))[lane];
            uint2 r7 = ((const uint2*)(H + (size_t)p7.x * 128))[lane];
            float c0 = __int_as_float(p0.y), c1 = __int_as_float(p1.y);
            float c2 = __int_as_float(p2.y), c3 = __int_as_float(p3.y);
            float c4 = __int_as_float(p4.y), c5 = __int_as_float(p5.y);
            float c6 = __int_as_float(p6.y), c7 = __int_as_float(p7.y);
            float2 a, b;
#define ACC_EDGE(rv, cv) \
            a = __half22float2(*(__half2*)&rv.x); b = __half22float2(*(__half2*)&rv.y); \
            acc.x = fmaf(a.x, cv, acc.x); acc.y = fmaf(a.y, cv, acc.y); \
            acc.z = fmaf(b.x, cv, acc.z); acc.w = fmaf(b.y, cv, acc.w);
            ACC_EDGE(r0, c0) ACC_EDGE(r1, c1) ACC_EDGE(r2, c2) ACC_EDGE(r3, c3)
            ACC_EDGE(r4, c4) ACC_EDGE(r5, c5) ACC_EDGE(r6, c6) ACC_EDGE(r7, c7)
        }
        for (; e < end; e++) {
            int2 pe = g_csr[e];
            float ce = __int_as_float(pe.y);
            uint2 r0 = ((const uint2*)(H + (size_t)pe.x * 128))[lane];
            float2 a, b;
            ACC_EDGE(r0, ce)
        }
#undef ACC_EDGE
        // fp16 store (stats from pre-rounding fp32)
        __half2 h0 = __floats2half2_rn(acc.x, acc.y);
        __half2 h1 = __floats2half2_rn(acc.z, acc.w);
        uint2 pk;
        pk.x = *(unsigned*)&h0; pk.y = *(unsigned*)&h1;
        ((uint2*)(Agg + (size_t)warp * 128))[lane] = pk;

        int col = lane << 2;
        atomicAdd(&sh_s[col + 0], acc.x);  atomicAdd(&sh_s2[col + 0], acc.x * acc.x);
        atomicAdd(&sh_s[col + 1], acc.y);  atomicAdd(&sh_s2[col + 1], acc.y * acc.y);
        atomicAdd(&sh_s[col + 2], acc.z);  atomicAdd(&sh_s2[col + 2], acc.z * acc.z);
        atomicAdd(&sh_s[col + 3], acc.w);  atomicAdd(&sh_s2[col + 3], acc.w * acc.w);
    }
    __syncthreads();
    if (threadIdx.x < 128) {
        atomicAdd(&g_stats[slot * 256 + threadIdx.x], sh_s[threadIdx.x]);
        atomicAdd(&g_stats[slot * 256 + 128 + threadIdx.x], sh_s2[threadIdx.x]);
    }
}

// ---- fused agg40 + bias + log-softmax: warp per node ----------------------
__global__ void agg40_logsm(const __half* __restrict__ H,
                            const float* __restrict__ b3,
                            float* __restrict__ out, int n) {
    const unsigned FULL = 0xffffffffu;
    int warp = (blockIdx.x * blockDim.x + threadIdx.x) >> 5;
    int lane = threadIdx.x & 31;
    if (warp >= n) return;
    int beg = g_off[warp], end = g_off[warp + 1];
    float4 acc = make_float4(0.f, 0.f, 0.f, 0.f);
    int e = beg;
    for (; e + 1 < end; e += 2) {
        int2 p0 = g_csr[e], p1 = g_csr[e + 1];
        float c0 = __int_as_float(p0.y), c1 = __int_as_float(p1.y);
        if (lane < 10) {
            uint2 r0 = ((const uint2*)(H + (size_t)p0.x * 40))[lane];
            uint2 r1 = ((const uint2*)(H + (size_t)p1.x * 40))[lane];
            float2 a0 = __half22float2(*(__half2*)&r0.x), b0 = __half22float2(*(__half2*)&r0.y);
            float2 a1 = __half22float2(*(__half2*)&r1.x), b1 = __half22float2(*(__half2*)&r1.y);
            acc.x = fmaf(a0.x, c0, fmaf(a1.x, c1, acc.x));
            acc.y = fmaf(a0.y, c0, fmaf(a1.y, c1, acc.y));
            acc.z = fmaf(b0.x, c0, fmaf(b1.x, c1, acc.z));
            acc.w = fmaf(b0.y, c0, fmaf(b1.y, c1, acc.w));
        }
    }
    if (e < end) {
        int2 p0 = g_csr[e];
        float c0 = __int_as_float(p0.y);
        if (lane < 10) {
            uint2 r0 = ((const uint2*)(H + (size_t)p0.x * 40))[lane];
            float2 a0 = __half22float2(*(__half2*)&r0.x), b0 = __half22float2(*(__half2*)&r0.y);
            acc.x = fmaf(a0.x, c0, acc.x);
            acc.y = fmaf(a0.y, c0, acc.y);
            acc.z = fmaf(b0.x, c0, acc.z);
            acc.w = fmaf(b0.y, c0, acc.w);
        }
    }
    float4 v = make_float4(-3.0e38f, -3.0e38f, -3.0e38f, -3.0e38f);
    if (lane < 10) {
        float4 bb = ((const float4*)b3)[lane];
        v = make_float4(acc.x + bb.x, acc.y + bb.y, acc.z + bb.z, acc.w + bb.w);
    }
    float mx = fmaxf(fmaxf(v.x, v.y), fmaxf(v.z, v.w));
#pragma unroll
    for (int o = 16; o; o >>= 1) mx = fmaxf(mx, __shfl_xor_sync(FULL, mx, o));
    float se = 0.f;
    if (lane < 10)
        se = expf(v.x - mx) + expf(v.y - mx) + expf(v.z - mx) + expf(v.w - mx);
#pragma unroll
    for (int o = 16; o; o >>= 1) se += __shfl_xor_sync(FULL, se, o);
    float sh = mx + logf(se);
    if (lane < 10)
        ((float4*)(out + (size_t)warp * 40))[lane] =
            make_float4(v.x - sh, v.y - sh, v.z - sh, v.w - sh);
}

// ---------------- launch ----------------
extern "C" void kernel_launch(void* const* d_in, const int* in_sizes, int n_in,
                              void* d_out, int out_size) {
    const float* feats = (const float*)d_in[0];
    const int*   ei    = (const int*)d_in[1];
    const float* W1 = (const float*)d_in[2];
    const float* g1 = (const float*)d_in[4];
    const float* be1 = (const float*)d_in[5];
    const float* W2 = (const float*)d_in[6];
    const float* g2 = (const float*)d_in[8];
    const float* be2 = (const float*)d_in[9];
    const float* W3 = (const float*)d_in[10];
    const float* b3 = (const float*)d_in[11];
    float* out = (float*)d_out;

    const int Nn = in_sizes[0] / HID;
    const int Ee = in_sizes[1] / 2;

    __half *hA, *hB, *h3;
    cudaGetSymbolAddress((void**)&hA, g_hA);
    cudaGetSymbolAddress((void**)&hB, g_hB);
    cudaGetSymbolAddress((void**)&h3, g_h3);

    const float invM = 1.0f / (float)Nn;
    const int nb = (Nn + 1023) / 1024;
    const int AGG_BLOCKS = (Nn + 7) / 8;       // warp per node, 8 warps/block

    // ---- degree + CSR build ----
    deg_init<<<(Nn + 255) / 256, 256>>>(Nn);
    deg_count<<<(Ee + 255) / 256, 256>>>(ei, Ee);
    scanA<<<nb, 1024>>>(Nn);
    scanC<<<nb, 1024>>>(Nn, nb);
    scatter_edges<<<(Ee + 255) / 256, 256>>>(ei, Ee);

    // ---- layer 1 ----
    gemm128_wmma<0><<<(Nn + 127) / 128, 256>>>(feats, W1, hA, Nn,
                                               nullptr, nullptr, 0, invM);
    agg_csr128<<<AGG_BLOCKS, 256>>>(hA, hB, Nn, 0);

    // ---- layer 2 (BN1+ReLU fused into A-load) ----
    gemm128_wmma<1><<<(Nn + 127) / 128, 256>>>(hB, W2, hA, Nn,
                                               g1, be1, 0, invM);
    agg_csr128<<<AGG_BLOCKS, 256>>>(hA, hB, Nn, 1);

    // ---- layer 3 (BN2+ReLU fused) ----
    gemm40_kernel<<<(Nn + 31) / 32, 256>>>(hB, W3, h3, Nn, g2, be2, invM);
    agg40_logsm<<<AGG_BLOCKS, 256>>>(h3, b3, out, Nn);
}